// round 4
// baseline (speedup 1.0000x reference)
#include <cuda_runtime.h>

#define Nn 10000
#define Ee 640000
#define Hh 128
#define Bb 64

// ---------------- scratch (device globals: no allocations allowed) ----------
__device__ float g_deg[Nn];
__device__ float g_dinv[Nn];
__device__ float g_norm[Ee];
__device__ float g_tmp[Nn * Hh];   // h @ W  (per layer)
__device__ float g_acc[Nn * Hh];   // scatter accumulator
__device__ float g_h[Nn * Hh];     // layer output / next layer input
__device__ float g_pool[Bb * Hh + Bb];  // pooled sums + counts tail

// ---------------- zero kernels ---------------------------------------------
__global__ void zero_deg_kernel() {
    int i = blockIdx.x * blockDim.x + threadIdx.x;
    if (i < Nn) g_deg[i] = 0.0f;
}

__global__ void zero_acc_kernel() {
    int i = blockIdx.x * blockDim.x + threadIdx.x;   // Nn*32 float4s
    if (i < Nn * (Hh / 4)) ((float4*)g_acc)[i] = make_float4(0.f, 0.f, 0.f, 0.f);
}

__global__ void zero_pool_kernel() {
    int i = blockIdx.x * blockDim.x + threadIdx.x;
    if (i < Bb * Hh + Bb) g_pool[i] = 0.0f;
}

// ---------------- degree / normalization -----------------------------------
__global__ void deg_kernel(const int* __restrict__ dst) {
    int e = blockIdx.x * blockDim.x + threadIdx.x;
    if (e < Ee) atomicAdd(&g_deg[dst[e]], 1.0f);
}

__global__ void dinv_kernel() {
    int i = blockIdx.x * blockDim.x + threadIdx.x;
    if (i < Nn) g_dinv[i] = rsqrtf(g_deg[i] + 1.0f);  // +1 self loop, deg>=1
}

__global__ void norm_kernel(const int* __restrict__ src, const int* __restrict__ dst) {
    int e = blockIdx.x * blockDim.x + threadIdx.x;
    if (e < Ee) g_norm[e] = g_dinv[src[e]] * g_dinv[dst[e]];
}

// ---------------- GEMM: g_tmp = A[Nn,128] @ W[128,128] ---------------------
// block: 256 threads, 64 rows x 128 cols per block, BK=32
__global__ void gemm_kernel(const float* __restrict__ A, const float* __restrict__ W) {
    __shared__ float As[64][32];
    __shared__ float Ws[32][128];

    int tid = threadIdx.x;
    int tx = tid & 31;    // column group: cols [tx*4, tx*4+3]
    int ty = tid >> 5;    // row group: rows [ty*8, ty*8+7]
    int rowBase = blockIdx.x * 64;

    float acc[8][4];
#pragma unroll
    for (int r = 0; r < 8; r++)
#pragma unroll
        for (int c = 0; c < 4; c++) acc[r][c] = 0.0f;

    for (int kk = 0; kk < Hh; kk += 32) {
#pragma unroll
        for (int i = 0; i < 2; i++) {
            int lin = tid * 2 + i;          // 0..511 float4 slots (64x8)
            int r = lin >> 3, c4 = lin & 7;
            int row = rowBase + r;
            float4 v = make_float4(0.f, 0.f, 0.f, 0.f);
            if (row < Nn) v = *(const float4*)&A[row * Hh + kk + c4 * 4];
            *(float4*)&As[r][c4 * 4] = v;
        }
#pragma unroll
        for (int i = 0; i < 4; i++) {
            int lin = i * 256 + tid;        // 0..1023 float4 slots (32x32)
            int r = lin >> 5, c4 = lin & 31;
            *(float4*)&Ws[r][c4 * 4] = *(const float4*)&W[(kk + r) * Hh + c4 * 4];
        }
        __syncthreads();
#pragma unroll
        for (int k = 0; k < 32; k++) {
            float4 b = *(float4*)&Ws[k][tx * 4];
#pragma unroll
            for (int r = 0; r < 8; r++) {
                float a = As[ty * 8 + r][k];
                acc[r][0] += a * b.x;
                acc[r][1] += a * b.y;
                acc[r][2] += a * b.z;
                acc[r][3] += a * b.w;
            }
        }
        __syncthreads();
    }
#pragma unroll
    for (int r = 0; r < 8; r++) {
        int row = rowBase + ty * 8 + r;
        if (row < Nn)
            *(float4*)&g_tmp[row * Hh + tx * 4] =
                make_float4(acc[r][0], acc[r][1], acc[r][2], acc[r][3]);
    }
}

// ---------------- edge scatter: acc[dst] += norm * tmp[src] -----------------
// one warp per edge, float4 per lane
__global__ void scatter_kernel(const int* __restrict__ src, const int* __restrict__ dst) {
    int t = blockIdx.x * blockDim.x + threadIdx.x;
    int e = t >> 5;
    int lane = t & 31;
    if (e >= Ee) return;
    int s = src[e];
    int d = dst[e];
    float nm = g_norm[e];
    float4 v = *(const float4*)&g_tmp[s * Hh + lane * 4];
    float* p = &g_acc[d * Hh + lane * 4];
    atomicAdd(p + 0, nm * v.x);
    atomicAdd(p + 1, nm * v.y);
    atomicAdd(p + 2, nm * v.z);
    atomicAdd(p + 3, nm * v.w);
}

// ---------------- epilogue: h = act(acc + dinv^2*tmp + b) -------------------
__global__ void finish_kernel(const float* __restrict__ bias, int relu) {
    int idx = blockIdx.x * blockDim.x + threadIdx.x;  // Nn*32 float4 slots
    if (idx >= Nn * (Hh / 4)) return;
    int i = idx >> 5;
    int jg = idx & 31;
    float di = g_dinv[i];
    float d2 = di * di;
    float4 a = ((const float4*)g_acc)[idx];
    float4 t = ((const float4*)g_tmp)[idx];
    float4 b = ((const float4*)bias)[jg];
    float4 r;
    r.x = a.x + d2 * t.x + b.x;
    r.y = a.y + d2 * t.y + b.y;
    r.z = a.z + d2 * t.z + b.z;
    r.w = a.w + d2 * t.w + b.w;
    if (relu) {
        r.x = fmaxf(r.x, 0.f);
        r.y = fmaxf(r.y, 0.f);
        r.z = fmaxf(r.z, 0.f);
        r.w = fmaxf(r.w, 0.f);
    }
    ((float4*)g_h)[idx] = r;
}

// ---------------- pooling ---------------------------------------------------
__global__ void pool_kernel(const int* __restrict__ batch) {
    int t = blockIdx.x * blockDim.x + threadIdx.x;
    int i = t >> 5;
    int lane = t & 31;
    if (i >= Nn) return;
    int b = batch[i];
    float4 v = ((const float4*)g_h)[i * 32 + lane];
    float* p = &g_pool[b * Hh + lane * 4];
    atomicAdd(p + 0, v.x);
    atomicAdd(p + 1, v.y);
    atomicAdd(p + 2, v.z);
    atomicAdd(p + 3, v.w);
    if (lane == 0) atomicAdd(&g_pool[Bb * Hh + b], 1.0f);
}

// ---------------- head: out[g] = dot(pool[g], Wp)/cnt[g] + bp ---------------
__global__ void head_kernel(const float* __restrict__ Wp, const float* __restrict__ bp,
                            float* __restrict__ out) {
    int t = blockIdx.x * blockDim.x + threadIdx.x;
    int g = t >> 5;
    int lane = t & 31;
    if (g >= Bb) return;
    float c = g_pool[Bb * Hh + g];
    float inv = 1.0f / fmaxf(c, 1.0f);
    float4 v = ((const float4*)g_pool)[g * 32 + lane];
    float4 w = ((const float4*)Wp)[lane];
    float s = v.x * w.x + v.y * w.y + v.z * w.z + v.w * w.w;
#pragma unroll
    for (int o = 16; o; o >>= 1) s += __shfl_xor_sync(0xffffffffu, s, o);
    if (lane == 0) out[g] = s * inv + bp[0];
}

// ---------------- launch ----------------------------------------------------
extern "C" void kernel_launch(void* const* d_in, const int* in_sizes, int n_in,
                              void* d_out, int out_size) {
    const float* x     = (const float*)d_in[0];
    const int*   ei    = (const int*)d_in[1];
    const int*   batch = (const int*)d_in[2];
    const float* W1    = (const float*)d_in[3];
    const float* b1    = (const float*)d_in[4];
    const float* W2    = (const float*)d_in[5];
    const float* b2    = (const float*)d_in[6];
    const float* W3    = (const float*)d_in[7];
    const float* b3    = (const float*)d_in[8];
    const float* Wp    = (const float*)d_in[9];
    const float* bp    = (const float*)d_in[10];
    float* out = (float*)d_out;

    const int* src = ei;        // edge_index[0]
    const int* dst = ei + Ee;   // edge_index[1]

    float* hbuf = nullptr;
    cudaGetSymbolAddress((void**)&hbuf, g_h);

    const int T = 256;
    int nb_N   = (Nn + T - 1) / T;                 // 40
    int nb_E   = (Ee + T - 1) / T;                 // 2500
    int nb_NH4 = (Nn * (Hh / 4) + T - 1) / T;      // 1250
    int nb_Ew  = (Ee * 32 + T - 1) / T;            // 80000
    int nb_Nw  = (Nn * 32 + T - 1) / T;            // 1250
    int nb_gemm = (Nn + 63) / 64;                  // 157

    // normalization precompute
    zero_deg_kernel<<<nb_N, T>>>();
    deg_kernel<<<nb_E, T>>>(dst);
    dinv_kernel<<<nb_N, T>>>();
    norm_kernel<<<nb_E, T>>>(src, dst);

    // layer 1
    gemm_kernel<<<nb_gemm, T>>>(x, W1);
    zero_acc_kernel<<<nb_NH4, T>>>();
    scatter_kernel<<<nb_Ew, T>>>(src, dst);
    finish_kernel<<<nb_NH4, T>>>(b1, 1);

    // layer 2
    gemm_kernel<<<nb_gemm, T>>>(hbuf, W2);
    zero_acc_kernel<<<nb_NH4, T>>>();
    scatter_kernel<<<nb_Ew, T>>>(src, dst);
    finish_kernel<<<nb_NH4, T>>>(b2, 1);

    // layer 3 (no relu)
    gemm_kernel<<<nb_gemm, T>>>(hbuf, W3);
    zero_acc_kernel<<<nb_NH4, T>>>();
    scatter_kernel<<<nb_Ew, T>>>(src, dst);
    finish_kernel<<<nb_NH4, T>>>(b3, 0);

    // pooling + head
    zero_pool_kernel<<<(Bb * Hh + Bb + T - 1) / T, T>>>();
    pool_kernel<<<nb_Nw, T>>>(batch);
    head_kernel<<<(Bb * 32 + T - 1) / T, T>>>(Wp, bp, out);
}

// round 5
// speedup vs baseline: 3.2778x; 3.2778x over previous
#include <cuda_runtime.h>

#define Nn 10000
#define Ee 640000
#define Hh 128
#define Bb 64

// ---------------- scratch (device globals) ----------------------------------
__device__ int   g_cnt[Nn];
__device__ int   g_off[Nn + 1];
__device__ int   g_cur[Nn];
__device__ int   g_csrc[Ee];     // CSR-ordered source node per incoming edge
__device__ float g_cnorm[Ee];    // CSR-ordered edge norm
__device__ float g_dinv[Nn];
__device__ float g_tmp[Nn * Hh]; // h @ W (per layer)
__device__ float g_h[Nn * Hh];   // layer output
__device__ float g_pool[Bb * Hh + Bb];

// ---------------- preprocessing ---------------------------------------------
__global__ void zero_cnt_kernel() {
    int i = blockIdx.x * blockDim.x + threadIdx.x;
    if (i < Nn) g_cnt[i] = 0;
}

__global__ void cnt_kernel(const int* __restrict__ dst) {
    int e = blockIdx.x * blockDim.x + threadIdx.x;
    if (e < Ee) atomicAdd(&g_cnt[dst[e]], 1);
}

// single-block exclusive scan of g_cnt -> g_off (1024 threads)
__global__ void scan_kernel() {
    __shared__ int wsum[32];
    __shared__ int carry_s;
    int t = threadIdx.x, lane = t & 31, w = t >> 5;
    if (t == 0) carry_s = 0;
    __syncthreads();
    for (int base = 0; base < Nn; base += 1024) {
        int i = base + t;
        int v = (i < Nn) ? g_cnt[i] : 0;
        int incl = v;
#pragma unroll
        for (int o = 1; o < 32; o <<= 1) {
            int x = __shfl_up_sync(0xffffffffu, incl, o);
            if (lane >= o) incl += x;
        }
        if (lane == 31) wsum[w] = incl;
        __syncthreads();
        if (w == 0) {
            int x = wsum[lane];
            int s2 = x;
#pragma unroll
            for (int o = 1; o < 32; o <<= 1) {
                int y = __shfl_up_sync(0xffffffffu, s2, o);
                if (lane >= o) s2 += y;
            }
            wsum[lane] = s2 - x;   // exclusive warp offsets
        }
        __syncthreads();
        int carry = carry_s;
        if (i < Nn) g_off[i] = carry + wsum[w] + incl - v;
        __syncthreads();
        if (t == 1023) carry_s = carry + wsum[31] + incl;
        __syncthreads();
    }
    if (threadIdx.x == 0) g_off[Nn] = carry_s;
}

__global__ void prep_kernel() {
    int i = blockIdx.x * blockDim.x + threadIdx.x;
    if (i < Nn) {
        g_dinv[i] = rsqrtf((float)g_cnt[i] + 1.0f);  // +1 self loop
        g_cur[i] = g_off[i];
    }
}

__global__ void fill_kernel(const int* __restrict__ src, const int* __restrict__ dst) {
    int e = blockIdx.x * blockDim.x + threadIdx.x;
    if (e >= Ee) return;
    int s = src[e];
    int d = dst[e];
    int pos = atomicAdd(&g_cur[d], 1);
    g_csrc[pos] = s;
    g_cnorm[pos] = g_dinv[s] * g_dinv[d];
}

// ---------------- GEMM: g_tmp = A[Nn,128] @ W[128,128] ----------------------
__global__ void gemm_kernel(const float* __restrict__ A, const float* __restrict__ W) {
    __shared__ float As[64][32];
    __shared__ float Ws[32][128];

    int tid = threadIdx.x;
    int tx = tid & 31;
    int ty = tid >> 5;
    int rowBase = blockIdx.x * 64;

    float acc[8][4];
#pragma unroll
    for (int r = 0; r < 8; r++)
#pragma unroll
        for (int c = 0; c < 4; c++) acc[r][c] = 0.0f;

    for (int kk = 0; kk < Hh; kk += 32) {
#pragma unroll
        for (int i = 0; i < 2; i++) {
            int lin = tid * 2 + i;
            int r = lin >> 3, c4 = lin & 7;
            int row = rowBase + r;
            float4 v = make_float4(0.f, 0.f, 0.f, 0.f);
            if (row < Nn) v = *(const float4*)&A[row * Hh + kk + c4 * 4];
            *(float4*)&As[r][c4 * 4] = v;
        }
#pragma unroll
        for (int i = 0; i < 4; i++) {
            int lin = i * 256 + tid;
            int r = lin >> 5, c4 = lin & 31;
            *(float4*)&Ws[r][c4 * 4] = *(const float4*)&W[(kk + r) * Hh + c4 * 4];
        }
        __syncthreads();
#pragma unroll
        for (int k = 0; k < 32; k++) {
            float4 b = *(float4*)&Ws[k][tx * 4];
#pragma unroll
            for (int r = 0; r < 8; r++) {
                float a = As[ty * 8 + r][k];
                acc[r][0] += a * b.x;
                acc[r][1] += a * b.y;
                acc[r][2] += a * b.z;
                acc[r][3] += a * b.w;
            }
        }
        __syncthreads();
    }
#pragma unroll
    for (int r = 0; r < 8; r++) {
        int row = rowBase + ty * 8 + r;
        if (row < Nn)
            *(float4*)&g_tmp[row * Hh + tx * 4] =
                make_float4(acc[r][0], acc[r][1], acc[r][2], acc[r][3]);
    }
}

// ---------------- fused gather + epilogue -----------------------------------
// one warp per destination node; register float4 accumulator; no atomics.
// mode: 1 = relu -> g_h, 0 = linear -> g_h, 2 = linear -> pool atomics
__global__ void gather_kernel(const float* __restrict__ bias, int mode,
                              const int* __restrict__ batch) {
    int t = blockIdx.x * blockDim.x + threadIdx.x;
    int i = t >> 5;          // node
    int lane = t & 31;
    if (i >= Nn) return;

    int beg = g_off[i];
    int end = g_off[i + 1];

    float4 acc = make_float4(0.f, 0.f, 0.f, 0.f);
    int p = beg;
    // 4-way unrolled main loop for MLP
    for (; p + 3 < end; p += 4) {
        int s0 = g_csrc[p + 0], s1 = g_csrc[p + 1], s2 = g_csrc[p + 2], s3 = g_csrc[p + 3];
        float n0 = g_cnorm[p + 0], n1 = g_cnorm[p + 1], n2 = g_cnorm[p + 2], n3 = g_cnorm[p + 3];
        float4 v0 = *(const float4*)&g_tmp[s0 * Hh + lane * 4];
        float4 v1 = *(const float4*)&g_tmp[s1 * Hh + lane * 4];
        float4 v2 = *(const float4*)&g_tmp[s2 * Hh + lane * 4];
        float4 v3 = *(const float4*)&g_tmp[s3 * Hh + lane * 4];
        acc.x += n0 * v0.x + n1 * v1.x + n2 * v2.x + n3 * v3.x;
        acc.y += n0 * v0.y + n1 * v1.y + n2 * v2.y + n3 * v3.y;
        acc.z += n0 * v0.z + n1 * v1.z + n2 * v2.z + n3 * v3.z;
        acc.w += n0 * v0.w + n1 * v1.w + n2 * v2.w + n3 * v3.w;
    }
    for (; p < end; p++) {
        int s = g_csrc[p];
        float nm = g_cnorm[p];
        float4 v = *(const float4*)&g_tmp[s * Hh + lane * 4];
        acc.x += nm * v.x;
        acc.y += nm * v.y;
        acc.z += nm * v.z;
        acc.w += nm * v.w;
    }

    // self-loop + bias
    float di = g_dinv[i];
    float d2 = di * di;
    float4 tv = ((const float4*)g_tmp)[i * 32 + lane];
    float4 b = ((const float4*)bias)[lane];
    float4 r;
    r.x = acc.x + d2 * tv.x + b.x;
    r.y = acc.y + d2 * tv.y + b.y;
    r.z = acc.z + d2 * tv.z + b.z;
    r.w = acc.w + d2 * tv.w + b.w;

    if (mode == 1) {
        r.x = fmaxf(r.x, 0.f);
        r.y = fmaxf(r.y, 0.f);
        r.z = fmaxf(r.z, 0.f);
        r.w = fmaxf(r.w, 0.f);
        ((float4*)g_h)[i * 32 + lane] = r;
    } else if (mode == 0) {
        ((float4*)g_h)[i * 32 + lane] = r;
    } else {
        // layer 3: pool directly, skip g_h round-trip
        int bg = batch[i];
        float* pp = &g_pool[bg * Hh + lane * 4];
        atomicAdd(pp + 0, r.x);
        atomicAdd(pp + 1, r.y);
        atomicAdd(pp + 2, r.z);
        atomicAdd(pp + 3, r.w);
        if (lane == 0) atomicAdd(&g_pool[Bb * Hh + bg], 1.0f);
    }
}

// ---------------- pooling tail ----------------------------------------------
__global__ void zero_pool_kernel() {
    int i = blockIdx.x * blockDim.x + threadIdx.x;
    if (i < Bb * Hh + Bb) g_pool[i] = 0.0f;
}

__global__ void head_kernel(const float* __restrict__ Wp, const float* __restrict__ bp,
                            float* __restrict__ out) {
    int t = blockIdx.x * blockDim.x + threadIdx.x;
    int g = t >> 5;
    int lane = t & 31;
    if (g >= Bb) return;
    float c = g_pool[Bb * Hh + g];
    float inv = 1.0f / fmaxf(c, 1.0f);
    float4 v = ((const float4*)g_pool)[g * 32 + lane];
    float4 w = ((const float4*)Wp)[lane];
    float s = v.x * w.x + v.y * w.y + v.z * w.z + v.w * w.w;
#pragma unroll
    for (int o = 16; o; o >>= 1) s += __shfl_xor_sync(0xffffffffu, s, o);
    if (lane == 0) out[g] = s * inv + bp[0];
}

// ---------------- launch ----------------------------------------------------
extern "C" void kernel_launch(void* const* d_in, const int* in_sizes, int n_in,
                              void* d_out, int out_size) {
    const float* x     = (const float*)d_in[0];
    const int*   ei    = (const int*)d_in[1];
    const int*   batch = (const int*)d_in[2];
    const float* W1    = (const float*)d_in[3];
    const float* b1    = (const float*)d_in[4];
    const float* W2    = (const float*)d_in[5];
    const float* b2    = (const float*)d_in[6];
    const float* W3    = (const float*)d_in[7];
    const float* b3    = (const float*)d_in[8];
    const float* Wp    = (const float*)d_in[9];
    const float* bp    = (const float*)d_in[10];
    float* out = (float*)d_out;

    const int* src = ei;        // edge_index[0]
    const int* dst = ei + Ee;   // edge_index[1]

    float* hbuf = nullptr;
    cudaGetSymbolAddress((void**)&hbuf, g_h);

    const int T = 256;
    int nb_N    = (Nn + T - 1) / T;             // 40
    int nb_E    = (Ee + T - 1) / T;             // 2500
    int nb_Nw   = (Nn * 32 + T - 1) / T;        // 1250
    int nb_gemm = (Nn + 63) / 64;               // 157

    // ---- CSR build + normalization (once, shared by all 3 layers) ----
    zero_cnt_kernel<<<nb_N, T>>>();
    cnt_kernel<<<nb_E, T>>>(dst);
    scan_kernel<<<1, 1024>>>();
    prep_kernel<<<nb_N, T>>>();
    fill_kernel<<<nb_E, T>>>(src, dst);
    zero_pool_kernel<<<(Bb * Hh + Bb + T - 1) / T, T>>>();

    // ---- layer 1 ----
    gemm_kernel<<<nb_gemm, T>>>(x, W1);
    gather_kernel<<<nb_Nw, T>>>(b1, 1, batch);

    // ---- layer 2 ----
    gemm_kernel<<<nb_gemm, T>>>(hbuf, W2);
    gather_kernel<<<nb_Nw, T>>>(b2, 1, batch);

    // ---- layer 3 (fused with pooling) ----
    gemm_kernel<<<nb_gemm, T>>>(hbuf, W3);
    gather_kernel<<<nb_Nw, T>>>(b3, 2, batch);

    // ---- head ----
    head_kernel<<<(Bb * 32 + T - 1) / T, T>>>(Wp, bp, out);
}